// round 10
// baseline (speedup 1.0000x reference)
#include <cuda_runtime.h>
#include <cuda_bf16.h>
#include <math.h>
#include <stdint.h>

#define NPIX 16384
#define WF 65
#define NF 8320
#define SMEM_FFT 75776

__device__ __align__(16) float2   g_xhat[(size_t)8 * 128 * NF];
__device__ __align__(16) float2   g_qkv [(size_t)8 * 384 * NF];
__device__ __align__(16) float    g_t   [(size_t)8 * 128 * NPIX];
__device__ __align__(16) float    g_attn[(size_t)8 * 128 * NPIX];
__device__ __align__(16) uint32_t g_wpk [640 * 128];

__device__ __forceinline__ float2 cadd(float2 a, float2 b){return make_float2(a.x+b.x,a.y+b.y);}
__device__ __forceinline__ float2 csub(float2 a, float2 b){return make_float2(a.x-b.x,a.y-b.y);}
__device__ __forceinline__ float2 cmul(float2 a, float2 b){return make_float2(a.x*b.x-a.y*b.y,a.x*b.y+a.y*b.x);}

__device__ __forceinline__ void warp_fft128(float2 v[4], const float2* __restrict__ Tw, int lane){
    float2 t0=cadd(v[0],v[2]), t1=csub(v[0],v[2]), t2=cadd(v[1],v[3]), t3=csub(v[1],v[3]);
    v[0]=cadd(t0,t2); v[2]=csub(t0,t2);
    v[1]=make_float2(t1.x+t3.y, t1.y-t3.x);
    v[3]=make_float2(t1.x-t3.y, t1.y+t3.x);
    v[1]=cmul(v[1],Tw[lane]); v[2]=cmul(v[2],Tw[(2*lane)&127]); v[3]=cmul(v[3],Tw[(3*lane)&127]);
#pragma unroll
    for(int h=16;h>=1;h>>=1){
        float2 w=Tw[(lane&(h-1))*(64/h)];
#pragma unroll
        for(int r=0;r<4;r++){
            float2 b;
            b.x=__shfl_xor_sync(0xffffffffu,v[r].x,h);
            b.y=__shfl_xor_sync(0xffffffffu,v[r].y,h);
            if(lane&h) v[r]=cmul(csub(b,v[r]),w); else v[r]=cadd(v[r],b);
        }
    }
}
__device__ __forceinline__ void fill_tw(float2* Tw, int tid){
    if(tid<128){ float s,c; sincospif(-(float)tid/64.0f,&s,&c); Tw[tid]=make_float2(c,s); }
}

__global__ __launch_bounds__(256) void fwd_rfft2_kernel(const float* __restrict__ src, float2* __restrict__ dst){
    extern __shared__ float sm[];
    float* FBr=sm; float* FBi=FBr+8320;
    float2* Zt=(float2*)(FBi+8320); float2* Tw=Zt+8*128;
    const int p=blockIdx.x, tid=threadIdx.x, lane=tid&31, wid=tid>>5;
    fill_tw(Tw,tid); __syncthreads();
    const float* xp=src+(size_t)p*NPIX;
    float2* zw=Zt+wid*128;
    for(int rp=wid;rp<64;rp+=8){
        int r0=2*rp, r1=r0+1;
        float2 v[4];
#pragma unroll
        for(int r=0;r<4;r++){ int j=lane+32*r; v[r]=make_float2(xp[r0*128+j],xp[r1*128+j]); }
        warp_fft128(v,Tw,lane);
        int rv=__brev(lane)>>27;
#pragma unroll
        for(int r=0;r<4;r++) zw[r+4*rv]=v[r];
        __syncwarp();
        for(int f=lane;f<WF;f+=32){
            float2 Zf=zw[f], Zm=zw[(128-f)&127];
            FBr[r0*WF+f]=0.5f*(Zf.x+Zm.x); FBi[r0*WF+f]=0.5f*(Zf.y-Zm.y);
            FBr[r1*WF+f]=0.5f*(Zf.y+Zm.y); FBi[r1*WF+f]=0.5f*(Zm.x-Zf.x);
        }
        __syncwarp();
    }
    __syncthreads();
    float2* dp=dst+(size_t)p*NF;
    for(int wf=wid;wf<WF;wf+=8){
        float2 v[4];
#pragma unroll
        for(int r=0;r<4;r++){ int hh=lane+32*r; v[r]=make_float2(FBr[hh*WF+wf],FBi[hh*WF+wf]); }
        warp_fft128(v,Tw,lane);
        int rv=__brev(lane)>>27;
#pragma unroll
        for(int r=0;r<4;r++) zw[r+4*rv]=v[r];
        __syncwarp();
        for(int j=lane;j<128;j+=32) dp[wf*128+j]=zw[j];
        __syncwarp();
    }
}

__global__ __launch_bounds__(256) void fused_attn_kernel(const float2* __restrict__ qkvb,
        const float* __restrict__ tmul, float* __restrict__ out){
    extern __shared__ float sm[];
    float* FBr=sm; float* FBi=FBr+8320;
    float2* Zt=(float2*)(FBi+8320); float2* Tw=Zt+8*128;
    __shared__ float red[16];
    const int p=blockIdx.x, b=p>>7, d=p&127;
    const int tid=threadIdx.x, lane=tid&31, wid=tid>>5;
    fill_tw(Tw,tid); __syncthreads();
    const float2* Qp=qkvb+(size_t)(b*384      +d)*NF;
    const float2* Kp=qkvb+(size_t)(b*384+128  +d)*NF;
    const float2* Vp=qkvb+(size_t)(b*384+256  +d)*NF;
    float2* zw=Zt+wid*128;
    const int rv=__brev(lane)>>27;
    for(int wf=wid;wf<WF;wf+=8){
        float2 v[4];
#pragma unroll
        for(int r=0;r<4;r++){
            int fi=wf*128+lane+32*r;
            float2 a=Qp[fi], bb=Kp[fi];
            v[r]=make_float2(a.x*bb.x+a.y*bb.y, a.y*bb.x-a.x*bb.y);
        }
        warp_fft128(v,Tw,lane);
#pragma unroll
        for(int r=0;r<4;r++){ int hh=r+4*rv; FBr[hh*WF+wf]=v[r].x; FBi[hh*WF+wf]=-v[r].y; }
    }
    __syncthreads();
    const float s1=1.0f/2097152.0f;
    for(int rp=wid;rp<64;rp+=8){
        int h0=2*rp, h1=h0+1;
        float2 v[4];
#pragma unroll
        for(int r=0;r<4;r++){
            int f=lane+32*r;
            if(f<WF){
                float g0x=FBr[h0*WF+f],g0y=FBi[h0*WF+f],g1x=FBr[h1*WF+f],g1y=FBi[h1*WF+f];
                v[r]=make_float2(g0x-g1y, -g0y-g1x);
            }else{
                int m=128-f;
                float g0x=FBr[h0*WF+m],g0y=FBi[h0*WF+m],g1x=FBr[h1*WF+m],g1y=FBi[h1*WF+m];
                v[r]=make_float2(g0x+g1y, g0y-g1x);
            }
        }
        warp_fft128(v,Tw,lane);
#pragma unroll
        for(int r=0;r<4;r++) zw[r+4*rv]=v[r];
        __syncwarp();
        for(int w=lane;w<128;w+=32){
            float2 z=zw[w];
            float v0=z.x*s1, v1=-z.y*s1;
            if(w<WF){ FBr[h0*WF+w]=v0; FBr[h1*WF+w]=v1; }
            else    { FBi[h0*WF+w-WF]=v0; FBi[h1*WF+w-WF]=v1; }
        }
        __syncwarp();
    }
    __syncthreads();
    float mx=-1e30f;
    for(int i=tid;i<NPIX;i+=256){
        int h=i>>7,w=i&127;
        float val=(w<WF)?FBr[h*WF+w]:FBi[h*WF+w-WF];
        mx=fmaxf(mx,val);
    }
    for(int o=16;o;o>>=1) mx=fmaxf(mx,__shfl_xor_sync(0xffffffffu,mx,o));
    if(lane==0) red[wid]=mx;
    __syncthreads();
    mx=red[0];
#pragma unroll
    for(int i=1;i<8;i++) mx=fmaxf(mx,red[i]);
    float s=0.f;
    for(int i=tid;i<NPIX;i+=256){
        int h=i>>7,w=i&127;
        float* a=(w<WF)?&FBr[h*WF+w]:&FBi[h*WF+w-WF];
        float e=expf(*a-mx); *a=e; s+=e;
    }
    for(int o=16;o;o>>=1) s+=__shfl_xor_sync(0xffffffffu,s,o);
    if(lane==0) red[8+wid]=s;
    __syncthreads();
    s=0.f;
#pragma unroll
    for(int i=0;i<8;i++) s+=red[8+i];
    float inv=1.0f/s;
    for(int i=tid;i<NPIX;i+=256){
        int h=i>>7,w=i&127;
        float* a=(w<WF)?&FBr[h*WF+w]:&FBi[h*WF+w-WF];
        *a*=inv;
    }
    __syncthreads();
    for(int rp=wid;rp<64;rp+=8){
        int r0=2*rp, r1=r0+1;
        float2 v[4];
#pragma unroll
        for(int r=0;r<4;r++){
            int j=lane+32*r;
            float a0=(j<WF)?FBr[r0*WF+j]:FBi[r0*WF+j-WF];
            float a1=(j<WF)?FBr[r1*WF+j]:FBi[r1*WF+j-WF];
            v[r]=make_float2(a0,a1);
        }
        warp_fft128(v,Tw,lane);
#pragma unroll
        for(int r=0;r<4;r++) zw[r+4*rv]=v[r];
        __syncwarp();
        for(int f=lane;f<WF;f+=32){
            float2 Zf=zw[f], Zm=zw[(128-f)&127];
            FBr[r0*WF+f]=0.5f*(Zf.x+Zm.x); FBi[r0*WF+f]=0.5f*(Zf.y-Zm.y);
            FBr[r1*WF+f]=0.5f*(Zf.y+Zm.y); FBi[r1*WF+f]=0.5f*(Zm.x-Zf.x);
        }
        __syncwarp();
    }
    __syncthreads();
    for(int wf=wid;wf<WF;wf+=8){
        float2 v[4];
#pragma unroll
        for(int r=0;r<4;r++){ int hh=lane+32*r; v[r]=make_float2(FBr[hh*WF+wf],FBi[hh*WF+wf]); }
        warp_fft128(v,Tw,lane);
#pragma unroll
        for(int r=0;r<4;r++) zw[r+4*rv]=v[r];
        __syncwarp();
#pragma unroll
        for(int r=0;r<4;r++){
            int k=lane+32*r;
            float2 A=zw[k], Vh=Vp[wf*128+k];
            v[r]=make_float2(A.x*Vh.x+A.y*Vh.y, A.y*Vh.x-A.x*Vh.y);
        }
        warp_fft128(v,Tw,lane);
#pragma unroll
        for(int r=0;r<4;r++){ int hh=r+4*rv; FBr[hh*WF+wf]=v[r].x; FBi[hh*WF+wf]=-v[r].y; }
        __syncwarp();
    }
    __syncthreads();
    const float s2=1.0f/16384.0f;
    float* op=out+(size_t)p*NPIX;
    const float* tp=tmul+(size_t)p*NPIX;
    for(int rp=wid;rp<64;rp+=8){
        int h0=2*rp, h1=h0+1;
        float2 v[4];
#pragma unroll
        for(int r=0;r<4;r++){
            int f=lane+32*r;
            if(f<WF){
                float g0x=FBr[h0*WF+f],g0y=FBi[h0*WF+f],g1x=FBr[h1*WF+f],g1y=FBi[h1*WF+f];
                v[r]=make_float2(g0x-g1y, -g0y-g1x);
            }else{
                int m=128-f;
                float g0x=FBr[h0*WF+m],g0y=FBi[h0*WF+m],g1x=FBr[h1*WF+m],g1y=FBi[h1*WF+m];
                v[r]=make_float2(g0x+g1y, g0y-g1x);
            }
        }
        warp_fft128(v,Tw,lane);
#pragma unroll
        for(int r=0;r<4;r++) zw[r+4*rv]=v[r];
        __syncwarp();
        for(int w=lane;w<128;w+=32){
            float2 z=zw[w];
            int i0=h0*128+w, i1=h1*128+w;
            op[i0]=z.x*s2*tp[i0];
            op[i1]=-z.y*s2*tp[i1];
        }
        __syncwarp();
    }
}

// ---------------- bf16 split ----------------
__device__ __forceinline__ uint32_t packsplit(float v){
    __nv_bfloat16 h=__float2bfloat16(v);
    float hf=__bfloat162float(h);
    __nv_bfloat16 l=__float2bfloat16(v-hf);
    return ((uint32_t)__bfloat16_as_ushort(h)<<16)|(uint32_t)__bfloat16_as_ushort(l);
}
__global__ void wpack(const float* __restrict__ src, uint32_t* __restrict__ dst, int n){
    int i=blockIdx.x*256+threadIdx.x;
    if(i<n) dst[i]=packsplit(src[i]);
}

// ---------------- mma.sync bf16 GEMM: ldmatrix + double-buffered k-steps ----------------
#define KW 68
#define HS_WH 0
#define HS_WL (128*KW)
#define HS_XH (2*128*KW)
#define HS_XL (3*128*KW)
#define HS_STG (4*128*KW)
#define HSM_TOT ((4*128*KW + 128*132)*4)

__device__ __forceinline__ uint32_t smem_u32(const void* p){
    uint32_t a; asm("{ .reg .u64 t; cvta.to.shared.u64 t, %1; cvt.u32.u64 %0, t; }":"=r"(a):"l"(p));
    return a;
}
__device__ __forceinline__ void mma_bf16(float c[4], const uint32_t a[4], const uint32_t b[2]){
    asm volatile("mma.sync.aligned.m16n8k16.row.col.f32.bf16.bf16.f32 "
        "{%0,%1,%2,%3}, {%4,%5,%6,%7}, {%8,%9}, {%0,%1,%2,%3};"
        : "+f"(c[0]),"+f"(c[1]),"+f"(c[2]),"+f"(c[3])
        : "r"(a[0]),"r"(a[1]),"r"(a[2]),"r"(a[3]),"r"(b[0]),"r"(b[1]));
}
#define LDSM4(d, addr) asm volatile("ldmatrix.sync.aligned.m8n8.x4.shared.b16 {%0,%1,%2,%3}, [%4];" \
    :"=r"((d)[0]),"=r"((d)[1]),"=r"((d)[2]),"=r"((d)[3]):"r"(addr))

__global__ __launch_bounds__(512,1) void hgemm(const uint32_t* __restrict__ Wq,
        const float* __restrict__ Xf, size_t xs, float* __restrict__ Cb, size_t cs,
        int ld, const float* __restrict__ bias, int act){
    extern __shared__ uint32_t hsm[];
    uint32_t* WH=hsm+HS_WH; uint32_t* WL=hsm+HS_WL;
    uint32_t* XH=hsm+HS_XH; uint32_t* XL=hsm+HS_XL;
    float* STG=(float*)(hsm+HS_STG);
    const int b=blockIdx.z, mt=blockIdx.y, nt=blockIdx.x;
    const int tid=threadIdx.x, wid=tid>>5, lane=tid&31;

    if(wid<8){
        const uint32_t* Wp=Wq+(size_t)mt*128*128;
        for(int idx=tid;idx<128*32;idx+=256){
            int row=idx>>5, c4=(idx&31)*4;
            uint4 w=*(const uint4*)&Wp[row*128+c4];
            uint32_t h0,l0,h1,l1;
            asm("prmt.b32 %0,%1,%2,0x7632;":"=r"(h0):"r"(w.x),"r"(w.y));
            asm("prmt.b32 %0,%1,%2,0x5410;":"=r"(l0):"r"(w.x),"r"(w.y));
            asm("prmt.b32 %0,%1,%2,0x7632;":"=r"(h1):"r"(w.z),"r"(w.w));
            asm("prmt.b32 %0,%1,%2,0x5410;":"=r"(l1):"r"(w.z),"r"(w.w));
            int wc=c4>>1;
            WH[row*KW+wc]=h0; WH[row*KW+wc+1]=h1;
            WL[row*KW+wc]=l0; WL[row*KW+wc+1]=l1;
        }
    }else{
        const int tid2=tid-256;
        const float* Xp=Xf+(size_t)b*xs+(size_t)nt*128;
        for(int idx=tid2;idx<128*32;idx+=256){
            int row=idx>>5, c4=(idx&31)*4;
            float4 v=*(const float4*)&Xp[(size_t)row*ld+c4];
            *(float4*)&STG[row*132+c4]=v;
        }
        asm volatile("bar.sync 1, 256;":::"memory");
        for(int idx=tid2;idx<128*64;idx+=256){
            int n=idx>>6, wc=idx&63;
            float f0=STG[(2*wc)*132+n], f1=STG[(2*wc+1)*132+n];
            uint32_t p0=packsplit(f0), p1=packsplit(f1);
            uint32_t hi,lo;
            asm("prmt.b32 %0,%1,%2,0x7632;":"=r"(hi):"r"(p0),"r"(p1));
            asm("prmt.b32 %0,%1,%2,0x5410;":"=r"(lo):"r"(p0),"r"(p1));
            XH[n*KW+wc]=hi; XL[n*KW+wc]=lo;
        }
    }
    __syncthreads();

    const int g=lane>>2, t=lane&3;
    const int warp_m=(wid>>2)*32, warp_n=(wid&3)*32;
    const int l8=lane&7;

    // ldmatrix lane addresses (bytes). A: groups 0-7:r0-7/c0, 8-15:r8-15/c0, 16-23:r0-7/c1, 24-31:r8-15/c1
    uint32_t aoff=((uint32_t)((warp_m + ((lane>>3)&1)*8 + l8)*KW + (lane>>4)*4))*4u;
    // B: groups 0-7:n0-7/c0, 8-15:n0-7/c1, 16-23:n8-15/c0, 24-31:n8-15/c1
    uint32_t boff=((uint32_t)((warp_n + (lane>>4)*8 + l8)*KW + ((lane>>3)&1)*4))*4u;
    const uint32_t shWH=smem_u32(WH)+aoff, shWL=smem_u32(WL)+aoff;
    const uint32_t shXH=smem_u32(XH)+boff, shXL=smem_u32(XL)+boff;
    const uint32_t MI=16u*KW*4u;   // +16 rows
    const uint32_t PI=16u*KW*4u;   // +16 n

    float acc[2][4][4];
#pragma unroll
    for(int mi=0;mi<2;mi++)
#pragma unroll
        for(int ni=0;ni<4;ni++)
#pragma unroll
            for(int q=0;q<4;q++) acc[mi][ni][q]=0.f;

    uint32_t AH[2][2][4], AL[2][2][4], BH[2][2][4], BL[2][2][4];

#define LOAD_FRAG(bu, kk) do{ \
        uint32_t ko=(uint32_t)(kk)*32u; \
        LDSM4(AH[bu][0], shWH+ko);     LDSM4(AH[bu][1], shWH+MI+ko); \
        LDSM4(AL[bu][0], shWL+ko);     LDSM4(AL[bu][1], shWL+MI+ko); \
        LDSM4(BH[bu][0], shXH+ko);     LDSM4(BH[bu][1], shXH+PI+ko); \
        LDSM4(BL[bu][0], shXL+ko);     LDSM4(BL[bu][1], shXL+PI+ko); \
    }while(0)

    LOAD_FRAG(0,0);
#pragma unroll
    for(int kk=0;kk<8;kk++){
        int cur=kk&1, nxt=cur^1;
        if(kk<7) LOAD_FRAG(nxt, kk+1);
#pragma unroll
        for(int mi=0;mi<2;mi++)
#pragma unroll
            for(int ni=0;ni<4;ni++){
                int pi=ni>>1, j=(ni&1)*2;
                mma_bf16(acc[mi][ni], AH[cur][mi], &BH[cur][pi][j]);
                mma_bf16(acc[mi][ni], AH[cur][mi], &BL[cur][pi][j]);
                mma_bf16(acc[mi][ni], AL[cur][mi], &BH[cur][pi][j]);
            }
    }

    float* C=Cb+(size_t)b*cs+(size_t)(mt*128)*ld+(size_t)nt*128;
#pragma unroll
    for(int mi=0;mi<2;mi++){
        int m0=warp_m+mi*16+g, m1=m0+8;
        float bv0=bias?bias[mt*128+m0]:0.f;
        float bv1=bias?bias[mt*128+m1]:0.f;
#pragma unroll
        for(int ni=0;ni<4;ni++){
            int cn=warp_n+ni*8+2*t;
            float v0=acc[mi][ni][0]+bv0, v1=acc[mi][ni][1]+bv0;
            float v2=acc[mi][ni][2]+bv1, v3=acc[mi][ni][3]+bv1;
            if(act){
                v0=v0/(1.0f+expf(-v0)); v1=v1/(1.0f+expf(-v1));
                v2=v2/(1.0f+expf(-v2)); v3=v3/(1.0f+expf(-v3));
            }
            *(float2*)&C[(size_t)m0*ld+cn]=make_float2(v0,v1);
            *(float2*)&C[(size_t)m1*ld+cn]=make_float2(v2,v3);
        }
    }
}

extern "C" void kernel_launch(void* const* d_in, const int* in_sizes, int n_in, void* d_out, int out_size){
    const float* x     =(const float*)d_in[0];
    const float* w_qkv =(const float*)d_in[1];
    const float* w_gate=(const float*)d_in[2];
    const float* b_gate=(const float*)d_in[3];
    const float* w_proj=(const float*)d_in[4];
    const float* b_proj=(const float*)d_in[5];
    float* out=(float*)d_out;

    cudaFuncSetAttribute(fwd_rfft2_kernel, cudaFuncAttributeMaxDynamicSharedMemorySize, SMEM_FFT);
    cudaFuncSetAttribute(fused_attn_kernel, cudaFuncAttributeMaxDynamicSharedMemorySize, SMEM_FFT);
    cudaFuncSetAttribute(hgemm, cudaFuncAttributeMaxDynamicSharedMemorySize, HSM_TOT);

    float2* xhat; cudaGetSymbolAddress((void**)&xhat, g_xhat);
    float2* qkv;  cudaGetSymbolAddress((void**)&qkv,  g_qkv);
    float*  tg;   cudaGetSymbolAddress((void**)&tg,   g_t);
    float*  attn; cudaGetSymbolAddress((void**)&attn, g_attn);
    uint32_t* wp; cudaGetSymbolAddress((void**)&wp,   g_wpk);

    uint32_t* wq=wp;
    uint32_t* wg=wp+384*128;
    uint32_t* wpj=wp+512*128;

    const size_t psN=(size_t)128*NPIX;
    const size_t fsX=(size_t)128*2*NF;
    const size_t fsQ=(size_t)384*2*NF;
    dim3 thr(256), t512(512);

    wpack<<<192,256>>>(w_qkv, wq, 384*128);
    wpack<<<64,256>>>(w_gate, wg, 128*128);
    wpack<<<64,256>>>(w_proj, wpj, 128*128);

    hgemm<<<dim3(128,1,8),t512,HSM_TOT>>>(wg, x, psN, tg, psN, NPIX, b_gate, 1);
    fwd_rfft2_kernel<<<1024,thr,SMEM_FFT>>>(x, xhat);
    hgemm<<<dim3(130,3,8),t512,HSM_TOT>>>(wq, (const float*)xhat, fsX, (float*)qkv, fsQ, 16640, 0, 0);
    fused_attn_kernel<<<1024,thr,SMEM_FFT>>>(qkv, tg, attn);
    hgemm<<<dim3(128,1,8),t512,HSM_TOT>>>(wpj, attn, psN, out, psN, NPIX, b_proj, 0);
}

// round 14
// speedup vs baseline: 1.2546x; 1.2546x over previous
#include <cuda_runtime.h>
#include <cuda_bf16.h>
#include <math.h>
#include <stdint.h>

#define NPIX 16384
#define WF 65
#define NF 8320
#define SMEM_FFT2 83968

__device__ __align__(16) float2   g_xhat[(size_t)8 * 128 * NF];
__device__ __align__(16) float2   g_qkv [(size_t)8 * 384 * NF];
__device__ __align__(16) float    g_t   [(size_t)8 * 128 * NPIX];
__device__ __align__(16) float    g_attn[(size_t)8 * 128 * NPIX];
__device__ __align__(16) uint32_t g_wpk [640 * 128];

__device__ __forceinline__ float2 cadd(float2 a, float2 b){return make_float2(a.x+b.x,a.y+b.y);}
__device__ __forceinline__ float2 csub(float2 a, float2 b){return make_float2(a.x-b.x,a.y-b.y);}
__device__ __forceinline__ float2 cmul(float2 a, float2 b){return make_float2(a.x*b.x-a.y*b.y,a.x*b.y+a.y*b.x);}

__device__ __forceinline__ void warp_fft128(float2 v[4], const float2* __restrict__ Tw, int lane){
    float2 t0=cadd(v[0],v[2]), t1=csub(v[0],v[2]), t2=cadd(v[1],v[3]), t3=csub(v[1],v[3]);
    v[0]=cadd(t0,t2); v[2]=csub(t0,t2);
    v[1]=make_float2(t1.x+t3.y, t1.y-t3.x);
    v[3]=make_float2(t1.x-t3.y, t1.y+t3.x);
    v[1]=cmul(v[1],Tw[lane]); v[2]=cmul(v[2],Tw[(2*lane)&127]); v[3]=cmul(v[3],Tw[(3*lane)&127]);
#pragma unroll
    for(int h=16;h>=1;h>>=1){
        float2 w=Tw[(lane&(h-1))*(64/h)];
#pragma unroll
        for(int r=0;r<4;r++){
            float2 b;
            b.x=__shfl_xor_sync(0xffffffffu,v[r].x,h);
            b.y=__shfl_xor_sync(0xffffffffu,v[r].y,h);
            if(lane&h) v[r]=cmul(csub(b,v[r]),w); else v[r]=cadd(v[r],b);
        }
    }
}
__device__ __forceinline__ void fill_tw(float2* Tw, int tid){
    if(tid<128){ float s,c; sincospif(-(float)tid/64.0f,&s,&c); Tw[tid]=make_float2(c,s); }
}

// ---------------- fwd rfft2, 512 threads / 16 warps ----------------
__global__ __launch_bounds__(512) void fwd_rfft2_kernel(const float* __restrict__ src, float2* __restrict__ dst){
    extern __shared__ float sm[];
    float* FBr=sm; float* FBi=FBr+8320;
    float2* Zt=(float2*)(FBi+8320); float2* Tw=Zt+16*128;
    const int p=blockIdx.x, tid=threadIdx.x, lane=tid&31, wid=tid>>5;
    fill_tw(Tw,tid); __syncthreads();
    const float* xp=src+(size_t)p*NPIX;
    float2* zw=Zt+wid*128;
    for(int rp=wid;rp<64;rp+=16){
        int r0=2*rp, r1=r0+1;
        float2 v[4];
#pragma unroll
        for(int r=0;r<4;r++){ int j=lane+32*r; v[r]=make_float2(xp[r0*128+j],xp[r1*128+j]); }
        warp_fft128(v,Tw,lane);
        int rv=__brev(lane)>>27;
#pragma unroll
        for(int r=0;r<4;r++) zw[r+4*rv]=v[r];
        __syncwarp();
        for(int f=lane;f<WF;f+=32){
            float2 Zf=zw[f], Zm=zw[(128-f)&127];
            FBr[r0*WF+f]=0.5f*(Zf.x+Zm.x); FBi[r0*WF+f]=0.5f*(Zf.y-Zm.y);
            FBr[r1*WF+f]=0.5f*(Zf.y+Zm.y); FBi[r1*WF+f]=0.5f*(Zm.x-Zf.x);
        }
        __syncwarp();
    }
    __syncthreads();
    float2* dp=dst+(size_t)p*NF;
    for(int wf=wid;wf<WF;wf+=16){
        float2 v[4];
#pragma unroll
        for(int r=0;r<4;r++){ int hh=lane+32*r; v[r]=make_float2(FBr[hh*WF+wf],FBi[hh*WF+wf]); }
        warp_fft128(v,Tw,lane);
        int rv=__brev(lane)>>27;
#pragma unroll
        for(int r=0;r<4;r++) zw[r+4*rv]=v[r];
        __syncwarp();
        for(int j=lane;j<128;j+=32) dp[wf*128+j]=zw[j];
        __syncwarp();
    }
}

// ---------------- fused attention, 512 threads / 16 warps ----------------
__global__ __launch_bounds__(512) void fused_attn_kernel(const float2* __restrict__ qkvb,
        const float* __restrict__ tmul, float* __restrict__ out){
    extern __shared__ float sm[];
    float* FBr=sm; float* FBi=FBr+8320;
    float2* Zt=(float2*)(FBi+8320); float2* Tw=Zt+16*128;
    __shared__ float red[32];
    const int p=blockIdx.x, b=p>>7, d=p&127;
    const int tid=threadIdx.x, lane=tid&31, wid=tid>>5;
    fill_tw(Tw,tid); __syncthreads();
    const float2* Qp=qkvb+(size_t)(b*384      +d)*NF;
    const float2* Kp=qkvb+(size_t)(b*384+128  +d)*NF;
    const float2* Vp=qkvb+(size_t)(b*384+256  +d)*NF;
    float2* zw=Zt+wid*128;
    const int rv=__brev(lane)>>27;
    for(int wf=wid;wf<WF;wf+=16){
        float2 v[4];
#pragma unroll
        for(int r=0;r<4;r++){
            int fi=wf*128+lane+32*r;
            float2 a=Qp[fi], bb=Kp[fi];
            v[r]=make_float2(a.x*bb.x+a.y*bb.y, a.y*bb.x-a.x*bb.y);
        }
        warp_fft128(v,Tw,lane);
#pragma unroll
        for(int r=0;r<4;r++){ int hh=r+4*rv; FBr[hh*WF+wf]=v[r].x; FBi[hh*WF+wf]=-v[r].y; }
    }
    __syncthreads();
    const float s1=1.0f/2097152.0f;
    for(int rp=wid;rp<64;rp+=16){
        int h0=2*rp, h1=h0+1;
        float2 v[4];
#pragma unroll
        for(int r=0;r<4;r++){
            int f=lane+32*r;
            if(f<WF){
                float g0x=FBr[h0*WF+f],g0y=FBi[h0*WF+f],g1x=FBr[h1*WF+f],g1y=FBi[h1*WF+f];
                v[r]=make_float2(g0x-g1y, -g0y-g1x);
            }else{
                int m=128-f;
                float g0x=FBr[h0*WF+m],g0y=FBi[h0*WF+m],g1x=FBr[h1*WF+m],g1y=FBi[h1*WF+m];
                v[r]=make_float2(g0x+g1y, g0y-g1x);
            }
        }
        warp_fft128(v,Tw,lane);
#pragma unroll
        for(int r=0;r<4;r++) zw[r+4*rv]=v[r];
        __syncwarp();
        for(int w=lane;w<128;w+=32){
            float2 z=zw[w];
            float v0=z.x*s1, v1=-z.y*s1;
            if(w<WF){ FBr[h0*WF+w]=v0; FBr[h1*WF+w]=v1; }
            else    { FBi[h0*WF+w-WF]=v0; FBi[h1*WF+w-WF]=v1; }
        }
        __syncwarp();
    }
    __syncthreads();
    float mx=-1e30f;
    for(int i=tid;i<NPIX;i+=512){
        int h=i>>7,w=i&127;
        float val=(w<WF)?FBr[h*WF+w]:FBi[h*WF+w-WF];
        mx=fmaxf(mx,val);
    }
    for(int o=16;o;o>>=1) mx=fmaxf(mx,__shfl_xor_sync(0xffffffffu,mx,o));
    if(lane==0) red[wid]=mx;
    __syncthreads();
    mx=red[0];
#pragma unroll
    for(int i=1;i<16;i++) mx=fmaxf(mx,red[i]);
    float s=0.f;
    for(int i=tid;i<NPIX;i+=512){
        int h=i>>7,w=i&127;
        float* a=(w<WF)?&FBr[h*WF+w]:&FBi[h*WF+w-WF];
        float e=expf(*a-mx); *a=e; s+=e;
    }
    for(int o=16;o;o>>=1) s+=__shfl_xor_sync(0xffffffffu,s,o);
    if(lane==0) red[16+wid]=s;
    __syncthreads();
    s=0.f;
#pragma unroll
    for(int i=0;i<16;i++) s+=red[16+i];
    float inv=1.0f/s;
    for(int i=tid;i<NPIX;i+=512){
        int h=i>>7,w=i&127;
        float* a=(w<WF)?&FBr[h*WF+w]:&FBi[h*WF+w-WF];
        *a*=inv;
    }
    __syncthreads();
    for(int rp=wid;rp<64;rp+=16){
        int r0=2*rp, r1=r0+1;
        float2 v[4];
#pragma unroll
        for(int r=0;r<4;r++){
            int j=lane+32*r;
            float a0=(j<WF)?FBr[r0*WF+j]:FBi[r0*WF+j-WF];
            float a1=(j<WF)?FBr[r1*WF+j]:FBi[r1*WF+j-WF];
            v[r]=make_float2(a0,a1);
        }
        warp_fft128(v,Tw,lane);
#pragma unroll
        for(int r=0;r<4;r++) zw[r+4*rv]=v[r];
        __syncwarp();
        for(int f=lane;f<WF;f+=32){
            float2 Zf=zw[f], Zm=zw[(128-f)&127];
            FBr[r0*WF+f]=0.5f*(Zf.x+Zm.x); FBi[r0*WF+f]=0.5f*(Zf.y-Zm.y);
            FBr[r1*WF+f]=0.5f*(Zf.y+Zm.y); FBi[r1*WF+f]=0.5f*(Zm.x-Zf.x);
        }
        __syncwarp();
    }
    __syncthreads();
    for(int wf=wid;wf<WF;wf+=16){
        float2 v[4];
#pragma unroll
        for(int r=0;r<4;r++){ int hh=lane+32*r; v[r]=make_float2(FBr[hh*WF+wf],FBi[hh*WF+wf]); }
        warp_fft128(v,Tw,lane);
#pragma unroll
        for(int r=0;r<4;r++) zw[r+4*rv]=v[r];
        __syncwarp();
#pragma unroll
        for(int r=0;r<4;r++){
            int k=lane+32*r;
            float2 A=zw[k], Vh=Vp[wf*128+k];
            v[r]=make_float2(A.x*Vh.x+A.y*Vh.y, A.y*Vh.x-A.x*Vh.y);
        }
        warp_fft128(v,Tw,lane);
#pragma unroll
        for(int r=0;r<4;r++){ int hh=r+4*rv; FBr[hh*WF+wf]=v[r].x; FBi[hh*WF+wf]=-v[r].y; }
        __syncwarp();
    }
    __syncthreads();
    const float s2=1.0f/16384.0f;
    float* op=out+(size_t)p*NPIX;
    const float* tp=tmul+(size_t)p*NPIX;
    for(int rp=wid;rp<64;rp+=16){
        int h0=2*rp, h1=h0+1;
        float2 v[4];
#pragma unroll
        for(int r=0;r<4;r++){
            int f=lane+32*r;
            if(f<WF){
                float g0x=FBr[h0*WF+f],g0y=FBi[h0*WF+f],g1x=FBr[h1*WF+f],g1y=FBi[h1*WF+f];
                v[r]=make_float2(g0x-g1y, -g0y-g1x);
            }else{
                int m=128-f;
                float g0x=FBr[h0*WF+m],g0y=FBi[h0*WF+m],g1x=FBr[h1*WF+m],g1y=FBi[h1*WF+m];
                v[r]=make_float2(g0x+g1y, g0y-g1x);
            }
        }
        warp_fft128(v,Tw,lane);
#pragma unroll
        for(int r=0;r<4;r++) zw[r+4*rv]=v[r];
        __syncwarp();
        for(int w=lane;w<128;w+=32){
            float2 z=zw[w];
            int i0=h0*128+w, i1=h1*128+w;
            op[i0]=z.x*s2*tp[i0];
            op[i1]=-z.y*s2*tp[i1];
        }
        __syncwarp();
    }
}

// ---------------- bf16 split ----------------
__device__ __forceinline__ uint32_t packsplit(float v){
    __nv_bfloat16 h=__float2bfloat16(v);
    float hf=__bfloat162float(h);
    __nv_bfloat16 l=__float2bfloat16(v-hf);
    return ((uint32_t)__bfloat16_as_ushort(h)<<16)|(uint32_t)__bfloat16_as_ushort(l);
}
__global__ void wpack(const float* __restrict__ src, uint32_t* __restrict__ dst, int n){
    int i=blockIdx.x*256+threadIdx.x;
    if(i<n) dst[i]=packsplit(src[i]);
}

// ---------------- hgemm: cp.async prefetch + multi-tile loop ----------------
#define KW 67
#define HS_WH 0
#define HS_WL (128*KW)
#define HS_XH (2*128*KW)
#define HS_XL (3*128*KW)
#define HS_STG (4*128*KW)
#define HSM_TOT ((4*128*KW + 128*132)*4)

__device__ __forceinline__ uint32_t smem_u32(const void* p){
    uint32_t a; asm("{ .reg .u64 t; cvta.to.shared.u64 t, %1; cvt.u32.u64 %0, t; }":"=r"(a):"l"(p));
    return a;
}
__device__ __forceinline__ void mma_bf16(float c[4], const uint32_t a[4], const uint32_t b[2]){
    asm volatile("mma.sync.aligned.m16n8k16.row.col.f32.bf16.bf16.f32 "
        "{%0,%1,%2,%3}, {%4,%5,%6,%7}, {%8,%9}, {%0,%1,%2,%3};"
        : "+f"(c[0]),"+f"(c[1]),"+f"(c[2]),"+f"(c[3])
        : "r"(a[0]),"r"(a[1]),"r"(a[2]),"r"(a[3]),"r"(b[0]),"r"(b[1]));
}
__device__ __forceinline__ void cp16(uint32_t saddr, const void* g){
    asm volatile("cp.async.cg.shared.global [%0], [%1], 16;"::"r"(saddr),"l"(g):"memory");
}

__global__ __launch_bounds__(512,1) void hgemm(const uint32_t* __restrict__ Wq,
        const float* __restrict__ Xf, size_t xs, float* __restrict__ Cb, size_t cs,
        int ld, const float* __restrict__ bias, int act, int nbat){
    extern __shared__ uint32_t hsm[];
    uint32_t* WH=hsm+HS_WH; uint32_t* WL=hsm+HS_WL;
    uint32_t* XH=hsm+HS_XH; uint32_t* XL=hsm+HS_XL;
    float* STG=(float*)(hsm+HS_STG);
    const uint32_t stg_b=smem_u32(STG);
    const int mt=blockIdx.y, nt=blockIdx.x, bz=blockIdx.z;
    const int tid=threadIdx.x, wid=tid>>5, lane=tid&31;
    const float* Xt0=Xf+(size_t)nt*128;

    // prefetch first X tile: 128 rows x 128 floats = 4096 float4s
    {
        const float* Xp=Xt0+(size_t)(bz*nbat)*xs;
        for(int c=tid;c<4096;c+=512){
            int row=c>>5, col=(c&31)*4;
            cp16(stg_b+(uint32_t)(row*132+col)*4u, Xp+(size_t)row*ld+col);
        }
        asm volatile("cp.async.commit_group;":::"memory");
    }
    // W load + split
    {
        const uint32_t* Wp=Wq+(size_t)mt*128*128;
        for(int idx=tid;idx<128*32;idx+=512){
            int row=idx>>5, c4=(idx&31)*4;
            uint4 w=*(const uint4*)&Wp[row*128+c4];
            uint32_t h0,l0,h1,l1;
            asm("prmt.b32 %0,%1,%2,0x7632;":"=r"(h0):"r"(w.x),"r"(w.y));
            asm("prmt.b32 %0,%1,%2,0x5410;":"=r"(l0):"r"(w.x),"r"(w.y));
            asm("prmt.b32 %0,%1,%2,0x7632;":"=r"(h1):"r"(w.z),"r"(w.w));
            asm("prmt.b32 %0,%1,%2,0x5410;":"=r"(l1):"r"(w.z),"r"(w.w));
            int wc=c4>>1;
            WH[row*KW+wc]=h0; WH[row*KW+wc+1]=h1;
            WL[row*KW+wc]=l0; WL[row*KW+wc+1]=l1;
        }
    }

    const int g=lane>>2, t=lane&3;
    const int warp_m=(wid>>2)*32, warp_n=(wid&3)*32;

    for(int nb=0;nb<nbat;nb++){
        const int b=bz*nbat+nb;
        asm volatile("cp.async.wait_group 0;":::"memory");
        __syncthreads();   // STG ready; prev mainloop done
        // transpose + split STG -> XH/XL: 8192 iterations (n 0..127, wc 0..63)
        for(int idx=tid;idx<8192;idx+=512){
            int n=idx&127, wc=idx>>7;
            float f0=STG[(2*wc)*132+n], f1=STG[(2*wc+1)*132+n];
            uint32_t p0=packsplit(f0), p1=packsplit(f1);
            uint32_t hi,lo;
            asm("prmt.b32 %0,%1,%2,0x7632;":"=r"(hi):"r"(p0),"r"(p1));
            asm("prmt.b32 %0,%1,%2,0x5410;":"=r"(lo):"r"(p0),"r"(p1));
            XH[n*KW+wc]=hi; XL[n*KW+wc]=lo;
        }
        __syncthreads();   // XH/XL ready; STG free for next prefetch
        if(nb+1<nbat){
            const float* Xp=Xt0+(size_t)(b+1)*xs;
            for(int c=tid;c<4096;c+=512){
                int row=c>>5, col=(c&31)*4;
                cp16(stg_b+(uint32_t)(row*132+col)*4u, Xp+(size_t)row*ld+col);
            }
            asm volatile("cp.async.commit_group;":::"memory");
        }

        float acc[2][4][4];
#pragma unroll
        for(int mi=0;mi<2;mi++)
#pragma unroll
            for(int ni=0;ni<4;ni++)
#pragma unroll
                for(int q=0;q<4;q++) acc[mi][ni][q]=0.f;

#pragma unroll
        for(int kk=0;kk<8;kk++){
            const int wt=kk*8+t;
            uint32_t bh[4][2], bl[4][2];
#pragma unroll
            for(int ni=0;ni<4;ni++){
                int n=warp_n+ni*8+g;
                bh[ni][0]=XH[n*KW+wt]; bh[ni][1]=XH[n*KW+wt+4];
                bl[ni][0]=XL[n*KW+wt]; bl[ni][1]=XL[n*KW+wt+4];
            }
#pragma unroll
            for(int mi=0;mi<2;mi++){
                int r0=warp_m+mi*16+g, r1=r0+8;
                uint32_t ah[4], al[4];
                ah[0]=WH[r0*KW+wt];   ah[1]=WH[r1*KW+wt];
                ah[2]=WH[r0*KW+wt+4]; ah[3]=WH[r1*KW+wt+4];
                al[0]=WL[r0*KW+wt];   al[1]=WL[r1*KW+wt];
                al[2]=WL[r0*KW+wt+4]; al[3]=WL[r1*KW+wt+4];
#pragma unroll
                for(int ni=0;ni<4;ni++){
                    mma_bf16(acc[mi][ni], ah, bh[ni]);
                    mma_bf16(acc[mi][ni], ah, bl[ni]);
                    mma_bf16(acc[mi][ni], al, bh[ni]);
                }
            }
        }

        float* C=Cb+(size_t)b*cs+(size_t)(mt*128)*ld+(size_t)nt*128;
#pragma unroll
        for(int mi=0;mi<2;mi++){
            int m0=warp_m+mi*16+g, m1=m0+8;
            float bv0=bias?bias[mt*128+m0]:0.f;
            float bv1=bias?bias[mt*128+m1]:0.f;
#pragma unroll
            for(int ni=0;ni<4;ni++){
                int cn=warp_n+ni*8+2*t;
                float v0=acc[mi][ni][0]+bv0, v1=acc[mi][ni][1]+bv0;
                float v2=acc[mi][ni][2]+bv1, v3=acc[mi][ni][3]+bv1;
                if(act){
                    v0=v0/(1.0f+expf(-v0)); v1=v1/(1.0f+expf(-v1));
                    v2=v2/(1.0f+expf(-v2)); v3=v3/(1.0f+expf(-v3));
                }
                *(float2*)&C[(size_t)m0*ld+cn]=make_float2(v0,v1);
                *(float2*)&C[(size_t)m1*ld+cn]=make_float2(v2,v3);
            }
        }
    }
}

extern "C" void kernel_launch(void* const* d_in, const int* in_sizes, int n_in, void* d_out, int out_size){
    const float* x     =(const float*)d_in[0];
    const float* w_qkv =(const float*)d_in[1];
    const float* w_gate=(const float*)d_in[2];
    const float* b_gate=(const float*)d_in[3];
    const float* w_proj=(const float*)d_in[4];
    const float* b_proj=(const float*)d_in[5];
    float* out=(float*)d_out;

    cudaFuncSetAttribute(fwd_rfft2_kernel, cudaFuncAttributeMaxDynamicSharedMemorySize, SMEM_FFT2);
    cudaFuncSetAttribute(fused_attn_kernel, cudaFuncAttributeMaxDynamicSharedMemorySize, SMEM_FFT2);
    cudaFuncSetAttribute(hgemm, cudaFuncAttributeMaxDynamicSharedMemorySize, HSM_TOT);

    float2* xhat; cudaGetSymbolAddress((void**)&xhat, g_xhat);
    float2* qkv;  cudaGetSymbolAddress((void**)&qkv,  g_qkv);
    float*  tg;   cudaGetSymbolAddress((void**)&tg,   g_t);
    float*  attn; cudaGetSymbolAddress((void**)&attn, g_attn);
    uint32_t* wp; cudaGetSymbolAddress((void**)&wp,   g_wpk);

    uint32_t* wq=wp;
    uint32_t* wg=wp+384*128;
    uint32_t* wpj=wp+512*128;

    const size_t psN=(size_t)128*NPIX;
    const size_t fsX=(size_t)128*2*NF;
    const size_t fsQ=(size_t)384*2*NF;
    dim3 t512(512);

    wpack<<<192,256>>>(w_qkv, wq, 384*128);
    wpack<<<64,256>>>(w_gate, wg, 128*128);
    wpack<<<64,256>>>(w_proj, wpj, 128*128);

    hgemm<<<dim3(128,1,1),t512,HSM_TOT>>>(wg, x, psN, tg, psN, NPIX, b_gate, 1, 8);
    fwd_rfft2_kernel<<<1024,t512,SMEM_FFT2>>>(x, xhat);
    hgemm<<<dim3(130,3,8),t512,HSM_TOT>>>(wq, (const float*)xhat, fsX, (float*)qkv, fsQ, 16640, 0, 0, 1);
    fused_attn_kernel<<<1024,t512,SMEM_FFT2>>>(qkv, tg, attn);
    hgemm<<<dim3(128,1,1),t512,HSM_TOT>>>(wpj, attn, psN, out, psN, NPIX, b_proj, 0, 8);
}

// round 15
// speedup vs baseline: 1.2913x; 1.0292x over previous
#include <cuda_runtime.h>
#include <cuda_bf16.h>
#include <math.h>
#include <stdint.h>

#define NPIX 16384
#define WF 65
#define NF 8320
#define SMEM_FFT2 83968

__device__ __align__(16) float2   g_xhat[(size_t)8 * 128 * NF];
__device__ __align__(16) float2   g_qkv [(size_t)8 * 384 * NF];
__device__ __align__(16) float    g_t   [(size_t)8 * 128 * NPIX];
__device__ __align__(16) float    g_attn[(size_t)8 * 128 * NPIX];
__device__ __align__(16) uint32_t g_wpk [640 * 128];

__device__ __forceinline__ float2 cadd(float2 a, float2 b){return make_float2(a.x+b.x,a.y+b.y);}
__device__ __forceinline__ float2 csub(float2 a, float2 b){return make_float2(a.x-b.x,a.y-b.y);}
__device__ __forceinline__ float2 cmul(float2 a, float2 b){return make_float2(a.x*b.x-a.y*b.y,a.x*b.y+a.y*b.x);}

__device__ __forceinline__ void warp_fft128(float2 v[4], const float2* __restrict__ Tw, int lane){
    float2 t0=cadd(v[0],v[2]), t1=csub(v[0],v[2]), t2=cadd(v[1],v[3]), t3=csub(v[1],v[3]);
    v[0]=cadd(t0,t2); v[2]=csub(t0,t2);
    v[1]=make_float2(t1.x+t3.y, t1.y-t3.x);
    v[3]=make_float2(t1.x-t3.y, t1.y+t3.x);
    v[1]=cmul(v[1],Tw[lane]); v[2]=cmul(v[2],Tw[(2*lane)&127]); v[3]=cmul(v[3],Tw[(3*lane)&127]);
#pragma unroll
    for(int h=16;h>=1;h>>=1){
        float2 w=Tw[(lane&(h-1))*(64/h)];
#pragma unroll
        for(int r=0;r<4;r++){
            float2 b;
            b.x=__shfl_xor_sync(0xffffffffu,v[r].x,h);
            b.y=__shfl_xor_sync(0xffffffffu,v[r].y,h);
            if(lane&h) v[r]=cmul(csub(b,v[r]),w); else v[r]=cadd(v[r],b);
        }
    }
}
__device__ __forceinline__ void fill_tw(float2* Tw, int tid){
    if(tid<128){ float s,c; sincospif(-(float)tid/64.0f,&s,&c); Tw[tid]=make_float2(c,s); }
}

// ---------------- fwd rfft2, 512 threads / 16 warps ----------------
__global__ __launch_bounds__(512) void fwd_rfft2_kernel(const float* __restrict__ src, float2* __restrict__ dst){
    extern __shared__ float sm[];
    float* FBr=sm; float* FBi=FBr+8320;
    float2* Zt=(float2*)(FBi+8320); float2* Tw=Zt+16*128;
    const int p=blockIdx.x, tid=threadIdx.x, lane=tid&31, wid=tid>>5;
    fill_tw(Tw,tid); __syncthreads();
    const float* xp=src+(size_t)p*NPIX;
    float2* zw=Zt+wid*128;
    for(int rp=wid;rp<64;rp+=16){
        int r0=2*rp, r1=r0+1;
        float2 v[4];
#pragma unroll
        for(int r=0;r<4;r++){ int j=lane+32*r; v[r]=make_float2(xp[r0*128+j],xp[r1*128+j]); }
        warp_fft128(v,Tw,lane);
        int rv=__brev(lane)>>27;
#pragma unroll
        for(int r=0;r<4;r++) zw[r+4*rv]=v[r];
        __syncwarp();
        for(int f=lane;f<WF;f+=32){
            float2 Zf=zw[f], Zm=zw[(128-f)&127];
            FBr[r0*WF+f]=0.5f*(Zf.x+Zm.x); FBi[r0*WF+f]=0.5f*(Zf.y-Zm.y);
            FBr[r1*WF+f]=0.5f*(Zf.y+Zm.y); FBi[r1*WF+f]=0.5f*(Zm.x-Zf.x);
        }
        __syncwarp();
    }
    __syncthreads();
    float2* dp=dst+(size_t)p*NF;
    for(int wf=wid;wf<WF;wf+=16){
        float2 v[4];
#pragma unroll
        for(int r=0;r<4;r++){ int hh=lane+32*r; v[r]=make_float2(FBr[hh*WF+wf],FBi[hh*WF+wf]); }
        warp_fft128(v,Tw,lane);
        int rv=__brev(lane)>>27;
#pragma unroll
        for(int r=0;r<4;r++) zw[r+4*rv]=v[r];
        __syncwarp();
        for(int j=lane;j<128;j+=32) dp[wf*128+j]=zw[j];
        __syncwarp();
    }
}

// ---------------- fused attention, 512 threads / 16 warps ----------------
__global__ __launch_bounds__(512) void fused_attn_kernel(const float2* __restrict__ qkvb,
        const float* __restrict__ tmul, float* __restrict__ out){
    extern __shared__ float sm[];
    float* FBr=sm; float* FBi=FBr+8320;
    float2* Zt=(float2*)(FBi+8320); float2* Tw=Zt+16*128;
    __shared__ float red[32];
    const int p=blockIdx.x, b=p>>7, d=p&127;
    const int tid=threadIdx.x, lane=tid&31, wid=tid>>5;
    fill_tw(Tw,tid); __syncthreads();
    const float2* Qp=qkvb+(size_t)(b*384      +d)*NF;
    const float2* Kp=qkvb+(size_t)(b*384+128  +d)*NF;
    const float2* Vp=qkvb+(size_t)(b*384+256  +d)*NF;
    float2* zw=Zt+wid*128;
    const int rv=__brev(lane)>>27;
    for(int wf=wid;wf<WF;wf+=16){
        float2 v[4];
#pragma unroll
        for(int r=0;r<4;r++){
            int fi=wf*128+lane+32*r;
            float2 a=Qp[fi], bb=Kp[fi];
            v[r]=make_float2(a.x*bb.x+a.y*bb.y, a.y*bb.x-a.x*bb.y);
        }
        warp_fft128(v,Tw,lane);
#pragma unroll
        for(int r=0;r<4;r++){ int hh=r+4*rv; FBr[hh*WF+wf]=v[r].x; FBi[hh*WF+wf]=-v[r].y; }
    }
    __syncthreads();
    const float s1=1.0f/2097152.0f;
    for(int rp=wid;rp<64;rp+=16){
        int h0=2*rp, h1=h0+1;
        float2 v[4];
#pragma unroll
        for(int r=0;r<4;r++){
            int f=lane+32*r;
            if(f<WF){
                float g0x=FBr[h0*WF+f],g0y=FBi[h0*WF+f],g1x=FBr[h1*WF+f],g1y=FBi[h1*WF+f];
                v[r]=make_float2(g0x-g1y, -g0y-g1x);
            }else{
                int m=128-f;
                float g0x=FBr[h0*WF+m],g0y=FBi[h0*WF+m],g1x=FBr[h1*WF+m],g1y=FBi[h1*WF+m];
                v[r]=make_float2(g0x+g1y, g0y-g1x);
            }
        }
        warp_fft128(v,Tw,lane);
#pragma unroll
        for(int r=0;r<4;r++) zw[r+4*rv]=v[r];
        __syncwarp();
        for(int w=lane;w<128;w+=32){
            float2 z=zw[w];
            float v0=z.x*s1, v1=-z.y*s1;
            if(w<WF){ FBr[h0*WF+w]=v0; FBr[h1*WF+w]=v1; }
            else    { FBi[h0*WF+w-WF]=v0; FBi[h1*WF+w-WF]=v1; }
        }
        __syncwarp();
    }
    __syncthreads();
    float mx=-1e30f;
    for(int i=tid;i<NPIX;i+=512){
        int h=i>>7,w=i&127;
        float val=(w<WF)?FBr[h*WF+w]:FBi[h*WF+w-WF];
        mx=fmaxf(mx,val);
    }
    for(int o=16;o;o>>=1) mx=fmaxf(mx,__shfl_xor_sync(0xffffffffu,mx,o));
    if(lane==0) red[wid]=mx;
    __syncthreads();
    mx=red[0];
#pragma unroll
    for(int i=1;i<16;i++) mx=fmaxf(mx,red[i]);
    float s=0.f;
    for(int i=tid;i<NPIX;i+=512){
        int h=i>>7,w=i&127;
        float* a=(w<WF)?&FBr[h*WF+w]:&FBi[h*WF+w-WF];
        float e=expf(*a-mx); *a=e; s+=e;
    }
    for(int o=16;o;o>>=1) s+=__shfl_xor_sync(0xffffffffu,s,o);
    if(lane==0) red[16+wid]=s;
    __syncthreads();
    s=0.f;
#pragma unroll
    for(int i=0;i<16;i++) s+=red[16+i];
    float inv=1.0f/s;
    for(int i=tid;i<NPIX;i+=512){
        int h=i>>7,w=i&127;
        float* a=(w<WF)?&FBr[h*WF+w]:&FBi[h*WF+w-WF];
        *a*=inv;
    }
    __syncthreads();
    for(int rp=wid;rp<64;rp+=16){
        int r0=2*rp, r1=r0+1;
        float2 v[4];
#pragma unroll
        for(int r=0;r<4;r++){
            int j=lane+32*r;
            float a0=(j<WF)?FBr[r0*WF+j]:FBi[r0*WF+j-WF];
            float a1=(j<WF)?FBr[r1*WF+j]:FBi[r1*WF+j-WF];
            v[r]=make_float2(a0,a1);
        }
        warp_fft128(v,Tw,lane);
#pragma unroll
        for(int r=0;r<4;r++) zw[r+4*rv]=v[r];
        __syncwarp();
        for(int f=lane;f<WF;f+=32){
            float2 Zf=zw[f], Zm=zw[(128-f)&127];
            FBr[r0*WF+f]=0.5f*(Zf.x+Zm.x); FBi[r0*WF+f]=0.5f*(Zf.y-Zm.y);
            FBr[r1*WF+f]=0.5f*(Zf.y+Zm.y); FBi[r1*WF+f]=0.5f*(Zm.x-Zf.x);
        }
        __syncwarp();
    }
    __syncthreads();
    for(int wf=wid;wf<WF;wf+=16){
        float2 v[4];
#pragma unroll
        for(int r=0;r<4;r++){ int hh=lane+32*r; v[r]=make_float2(FBr[hh*WF+wf],FBi[hh*WF+wf]); }
        warp_fft128(v,Tw,lane);
#pragma unroll
        for(int r=0;r<4;r++) zw[r+4*rv]=v[r];
        __syncwarp();
#pragma unroll
        for(int r=0;r<4;r++){
            int k=lane+32*r;
            float2 A=zw[k], Vh=Vp[wf*128+k];
            v[r]=make_float2(A.x*Vh.x+A.y*Vh.y, A.y*Vh.x-A.x*Vh.y);
        }
        warp_fft128(v,Tw,lane);
#pragma unroll
        for(int r=0;r<4;r++){ int hh=r+4*rv; FBr[hh*WF+wf]=v[r].x; FBi[hh*WF+wf]=-v[r].y; }
        __syncwarp();
    }
    __syncthreads();
    const float s2=1.0f/16384.0f;
    float* op=out+(size_t)p*NPIX;
    const float* tp=tmul+(size_t)p*NPIX;
    for(int rp=wid;rp<64;rp+=16){
        int h0=2*rp, h1=h0+1;
        float2 v[4];
#pragma unroll
        for(int r=0;r<4;r++){
            int f=lane+32*r;
            if(f<WF){
                float g0x=FBr[h0*WF+f],g0y=FBi[h0*WF+f],g1x=FBr[h1*WF+f],g1y=FBi[h1*WF+f];
                v[r]=make_float2(g0x-g1y, -g0y-g1x);
            }else{
                int m=128-f;
                float g0x=FBr[h0*WF+m],g0y=FBi[h0*WF+m],g1x=FBr[h1*WF+m],g1y=FBi[h1*WF+m];
                v[r]=make_float2(g0x+g1y, g0y-g1x);
            }
        }
        warp_fft128(v,Tw,lane);
#pragma unroll
        for(int r=0;r<4;r++) zw[r+4*rv]=v[r];
        __syncwarp();
        for(int w=lane;w<128;w+=32){
            float2 z=zw[w];
            int i0=h0*128+w, i1=h1*128+w;
            op[i0]=z.x*s2*tp[i0];
            op[i1]=-z.y*s2*tp[i1];
        }
        __syncwarp();
    }
}

// ---------------- bf16 split ----------------
__device__ __forceinline__ uint32_t packsplit(float v){
    __nv_bfloat16 h=__float2bfloat16(v);
    float hf=__bfloat162float(h);
    __nv_bfloat16 l=__float2bfloat16(v-hf);
    return ((uint32_t)__bfloat16_as_ushort(h)<<16)|(uint32_t)__bfloat16_as_ushort(l);
}
__global__ void wpack(const float* __restrict__ src, uint32_t* __restrict__ dst, int n){
    int i=blockIdx.x*256+threadIdx.x;
    if(i<n) dst[i]=packsplit(src[i]);
}

// ---------------- hgemm: cp.async prefetch + multi-tile loop ----------------
#define KW 67
#define HS_WH 0
#define HS_WL (128*KW)
#define HS_XH (2*128*KW)
#define HS_XL (3*128*KW)
#define HS_STG (4*128*KW)
#define HSM_TOT ((4*128*KW + 128*132)*4)

__device__ __forceinline__ uint32_t smem_u32(const void* p){
    uint32_t a; asm("{ .reg .u64 t; cvta.to.shared.u64 t, %1; cvt.u32.u64 %0, t; }":"=r"(a):"l"(p));
    return a;
}
__device__ __forceinline__ void mma_bf16(float c[4], const uint32_t a[4], const uint32_t b[2]){
    asm volatile("mma.sync.aligned.m16n8k16.row.col.f32.bf16.bf16.f32 "
        "{%0,%1,%2,%3}, {%4,%5,%6,%7}, {%8,%9}, {%0,%1,%2,%3};"
        : "+f"(c[0]),"+f"(c[1]),"+f"(c[2]),"+f"(c[3])
        : "r"(a[0]),"r"(a[1]),"r"(a[2]),"r"(a[3]),"r"(b[0]),"r"(b[1]));
}
__device__ __forceinline__ void cp16(uint32_t saddr, const void* g){
    asm volatile("cp.async.cg.shared.global [%0], [%1], 16;"::"r"(saddr),"l"(g):"memory");
}

__global__ __launch_bounds__(512,1) void hgemm(const uint32_t* __restrict__ Wq,
        const float* __restrict__ Xf, size_t xs, float* __restrict__ Cb, size_t cs,
        int ld, const float* __restrict__ bias, int act, int nbat){
    extern __shared__ uint32_t hsm[];
    uint32_t* WH=hsm+HS_WH; uint32_t* WL=hsm+HS_WL;
    uint32_t* XH=hsm+HS_XH; uint32_t* XL=hsm+HS_XL;
    float* STG=(float*)(hsm+HS_STG);
    const uint32_t stg_b=smem_u32(STG);
    const int mt=blockIdx.y, nt=blockIdx.x, bz=blockIdx.z;
    const int tid=threadIdx.x, wid=tid>>5, lane=tid&31;
    const float* Xt0=Xf+(size_t)nt*128;

    {
        const float* Xp=Xt0+(size_t)(bz*nbat)*xs;
        for(int c=tid;c<4096;c+=512){
            int row=c>>5, col=(c&31)*4;
            cp16(stg_b+(uint32_t)(row*132+col)*4u, Xp+(size_t)row*ld+col);
        }
        asm volatile("cp.async.commit_group;":::"memory");
    }
    {
        const uint32_t* Wp=Wq+(size_t)mt*128*128;
        for(int idx=tid;idx<128*32;idx+=512){
            int row=idx>>5, c4=(idx&31)*4;
            uint4 w=*(const uint4*)&Wp[row*128+c4];
            uint32_t h0,l0,h1,l1;
            asm("prmt.b32 %0,%1,%2,0x7632;":"=r"(h0):"r"(w.x),"r"(w.y));
            asm("prmt.b32 %0,%1,%2,0x5410;":"=r"(l0):"r"(w.x),"r"(w.y));
            asm("prmt.b32 %0,%1,%2,0x7632;":"=r"(h1):"r"(w.z),"r"(w.w));
            asm("prmt.b32 %0,%1,%2,0x5410;":"=r"(l1):"r"(w.z),"r"(w.w));
            int wc=c4>>1;
            WH[row*KW+wc]=h0; WH[row*KW+wc+1]=h1;
            WL[row*KW+wc]=l0; WL[row*KW+wc+1]=l1;
        }
    }

    const int g=lane>>2, t=lane&3;
    const int warp_m=(wid>>2)*32, warp_n=(wid&3)*32;

    for(int nb=0;nb<nbat;nb++){
        const int b=bz*nbat+nb;
        asm volatile("cp.async.wait_group 0;":::"memory");
        __syncthreads();
        for(int idx=tid;idx<8192;idx+=512){
            int n=idx&127, wc=idx>>7;
            float f0=STG[(2*wc)*132+n], f1=STG[(2*wc+1)*132+n];
            uint32_t p0=packsplit(f0), p1=packsplit(f1);
            uint32_t hi,lo;
            asm("prmt.b32 %0,%1,%2,0x7632;":"=r"(hi):"r"(p0),"r"(p1));
            asm("prmt.b32 %0,%1,%2,0x5410;":"=r"(lo):"r"(p0),"r"(p1));
            XH[n*KW+wc]=hi; XL[n*KW+wc]=lo;
        }
        __syncthreads();
        if(nb+1<nbat){
            const float* Xp=Xt0+(size_t)(b+1)*xs;
            for(int c=tid;c<4096;c+=512){
                int row=c>>5, col=(c&31)*4;
                cp16(stg_b+(uint32_t)(row*132+col)*4u, Xp+(size_t)row*ld+col);
            }
            asm volatile("cp.async.commit_group;":::"memory");
        }

        float acc[2][4][4];
#pragma unroll
        for(int mi=0;mi<2;mi++)
#pragma unroll
            for(int ni=0;ni<4;ni++)
#pragma unroll
                for(int q=0;q<4;q++) acc[mi][ni][q]=0.f;

#pragma unroll
        for(int kk=0;kk<8;kk++){
            const int wt=kk*8+t;
            uint32_t bh[4][2], bl[4][2];
#pragma unroll
            for(int ni=0;ni<4;ni++){
                int n=warp_n+ni*8+g;
                bh[ni][0]=XH[n*KW+wt]; bh[ni][1]=XH[n*KW+wt+4];
                bl[ni][0]=XL[n*KW+wt]; bl[ni][1]=XL[n*KW+wt+4];
            }
#pragma unroll
            for(int mi=0;mi<2;mi++){
                int r0=warp_m+mi*16+g, r1=r0+8;
                uint32_t ah[4], al[4];
                ah[0]=WH[r0*KW+wt];   ah[1]=WH[r1*KW+wt];
                ah[2]=WH[r0*KW+wt+4]; ah[3]=WH[r1*KW+wt+4];
                al[0]=WL[r0*KW+wt];   al[1]=WL[r1*KW+wt];
                al[2]=WL[r0*KW+wt+4]; al[3]=WL[r1*KW+wt+4];
#pragma unroll
                for(int ni=0;ni<4;ni++){
                    mma_bf16(acc[mi][ni], ah, bh[ni]);
                    mma_bf16(acc[mi][ni], ah, bl[ni]);
                    mma_bf16(acc[mi][ni], al, bh[ni]);
                }
            }
        }

        float* C=Cb+(size_t)b*cs+(size_t)(mt*128)*ld+(size_t)nt*128;
#pragma unroll
        for(int mi=0;mi<2;mi++){
            int m0=warp_m+mi*16+g, m1=m0+8;
            float bv0=bias?bias[mt*128+m0]:0.f;
            float bv1=bias?bias[mt*128+m1]:0.f;
#pragma unroll
            for(int ni=0;ni<4;ni++){
                int cn=warp_n+ni*8+2*t;
                float v0=acc[mi][ni][0]+bv0, v1=acc[mi][ni][1]+bv0;
                float v2=acc[mi][ni][2]+bv1, v3=acc[mi][ni][3]+bv1;
                if(act){
                    v0=v0/(1.0f+expf(-v0)); v1=v1/(1.0f+expf(-v1));
                    v2=v2/(1.0f+expf(-v2)); v3=v3/(1.0f+expf(-v3));
                }
                *(float2*)&C[(size_t)m0*ld+cn]=make_float2(v0,v1);
                *(float2*)&C[(size_t)m1*ld+cn]=make_float2(v2,v3);
            }
        }
    }
}

extern "C" void kernel_launch(void* const* d_in, const int* in_sizes, int n_in, void* d_out, int out_size){
    const float* x     =(const float*)d_in[0];
    const float* w_qkv =(const float*)d_in[1];
    const float* w_gate=(const float*)d_in[2];
    const float* b_gate=(const float*)d_in[3];
    const float* w_proj=(const float*)d_in[4];
    const float* b_proj=(const float*)d_in[5];
    float* out=(float*)d_out;

    cudaFuncSetAttribute(fwd_rfft2_kernel, cudaFuncAttributeMaxDynamicSharedMemorySize, SMEM_FFT2);
    cudaFuncSetAttribute(fused_attn_kernel, cudaFuncAttributeMaxDynamicSharedMemorySize, SMEM_FFT2);
    cudaFuncSetAttribute(hgemm, cudaFuncAttributeMaxDynamicSharedMemorySize, HSM_TOT);

    float2* xhat; cudaGetSymbolAddress((void**)&xhat, g_xhat);
    float2* qkv;  cudaGetSymbolAddress((void**)&qkv,  g_qkv);
    float*  tg;   cudaGetSymbolAddress((void**)&tg,   g_t);
    float*  attn; cudaGetSymbolAddress((void**)&attn, g_attn);
    uint32_t* wp; cudaGetSymbolAddress((void**)&wp,   g_wpk);

    uint32_t* wq=wp;
    uint32_t* wg=wp+384*128;
    uint32_t* wpj=wp+512*128;

    const size_t psN=(size_t)128*NPIX;
    const size_t fsX=(size_t)128*2*NF;
    const size_t fsQ=(size_t)384*2*NF;
    dim3 t512(512);

    wpack<<<192,256>>>(w_qkv, wq, 384*128);
    wpack<<<64,256>>>(w_gate, wg, 128*128);
    wpack<<<64,256>>>(w_proj, wpj, 128*128);

    hgemm<<<dim3(128,1,1),t512,HSM_TOT>>>(wg, x, psN, tg, psN, NPIX, b_gate, 1, 8);
    fwd_rfft2_kernel<<<1024,t512,SMEM_FFT2>>>(x, xhat);
    hgemm<<<dim3(130,3,1),t512,HSM_TOT>>>(wq, (const float*)xhat, fsX, (float*)qkv, fsQ, 16640, 0, 0, 8);
    fused_attn_kernel<<<1024,t512,SMEM_FFT2>>>(qkv, tg, attn);
    hgemm<<<dim3(128,1,1),t512,HSM_TOT>>>(wpj, attn, psN, out, psN, NPIX, b_proj, 0, 8);
}

// round 16
// speedup vs baseline: 1.2942x; 1.0022x over previous
#include <cuda_runtime.h>
#include <cuda_bf16.h>
#include <math.h>
#include <stdint.h>

#define NPIX 16384
#define WF 65
#define NF 8320
#define SMEM_FFT2 83968

__device__ __align__(16) float2   g_xhat[(size_t)8 * 128 * NF];
__device__ __align__(16) float2   g_qkv [(size_t)8 * 384 * NF];
__device__ __align__(16) float    g_t   [(size_t)8 * 128 * NPIX];
__device__ __align__(16) float    g_attn[(size_t)8 * 128 * NPIX];
__device__ __align__(16) uint32_t g_wpk [640 * 128];

__device__ __forceinline__ float2 cadd(float2 a, float2 b){return make_float2(a.x+b.x,a.y+b.y);}
__device__ __forceinline__ float2 csub(float2 a, float2 b){return make_float2(a.x-b.x,a.y-b.y);}
__device__ __forceinline__ float2 cmul(float2 a, float2 b){return make_float2(a.x*b.x-a.y*b.y,a.x*b.y+a.y*b.x);}

__device__ __forceinline__ void warp_fft128(float2 v[4], const float2* __restrict__ Tw, int lane){
    float2 t0=cadd(v[0],v[2]), t1=csub(v[0],v[2]), t2=cadd(v[1],v[3]), t3=csub(v[1],v[3]);
    v[0]=cadd(t0,t2); v[2]=csub(t0,t2);
    v[1]=make_float2(t1.x+t3.y, t1.y-t3.x);
    v[3]=make_float2(t1.x-t3.y, t1.y+t3.x);
    v[1]=cmul(v[1],Tw[lane]); v[2]=cmul(v[2],Tw[(2*lane)&127]); v[3]=cmul(v[3],Tw[(3*lane)&127]);
#pragma unroll
    for(int h=16;h>=1;h>>=1){
        float2 w=Tw[(lane&(h-1))*(64/h)];
#pragma unroll
        for(int r=0;r<4;r++){
            float2 b;
            b.x=__shfl_xor_sync(0xffffffffu,v[r].x,h);
            b.y=__shfl_xor_sync(0xffffffffu,v[r].y,h);
            if(lane&h) v[r]=cmul(csub(b,v[r]),w); else v[r]=cadd(v[r],b);
        }
    }
}
__device__ __forceinline__ void fill_tw(float2* Tw, int tid){
    if(tid<128){ float s,c; sincospif(-(float)tid/64.0f,&s,&c); Tw[tid]=make_float2(c,s); }
}

// ---------------- fwd rfft2, 512 threads / 16 warps, 2 CTAs/SM ----------------
__global__ __launch_bounds__(512,2) void fwd_rfft2_kernel(const float* __restrict__ src, float2* __restrict__ dst){
    extern __shared__ float sm[];
    float* FBr=sm; float* FBi=FBr+8320;
    float2* Zt=(float2*)(FBi+8320); float2* Tw=Zt+16*128;
    const int p=blockIdx.x, tid=threadIdx.x, lane=tid&31, wid=tid>>5;
    fill_tw(Tw,tid); __syncthreads();
    const float* xp=src+(size_t)p*NPIX;
    float2* zw=Zt+wid*128;
    for(int rp=wid;rp<64;rp+=16){
        int r0=2*rp, r1=r0+1;
        float2 v[4];
#pragma unroll
        for(int r=0;r<4;r++){ int j=lane+32*r; v[r]=make_float2(xp[r0*128+j],xp[r1*128+j]); }
        warp_fft128(v,Tw,lane);
        int rv=__brev(lane)>>27;
#pragma unroll
        for(int r=0;r<4;r++) zw[r+4*rv]=v[r];
        __syncwarp();
        for(int f=lane;f<WF;f+=32){
            float2 Zf=zw[f], Zm=zw[(128-f)&127];
            FBr[r0*WF+f]=0.5f*(Zf.x+Zm.x); FBi[r0*WF+f]=0.5f*(Zf.y-Zm.y);
            FBr[r1*WF+f]=0.5f*(Zf.y+Zm.y); FBi[r1*WF+f]=0.5f*(Zm.x-Zf.x);
        }
        __syncwarp();
    }
    __syncthreads();
    float2* dp=dst+(size_t)p*NF;
    for(int wf=wid;wf<WF;wf+=16){
        float2 v[4];
#pragma unroll
        for(int r=0;r<4;r++){ int hh=lane+32*r; v[r]=make_float2(FBr[hh*WF+wf],FBi[hh*WF+wf]); }
        warp_fft128(v,Tw,lane);
        int rv=__brev(lane)>>27;
#pragma unroll
        for(int r=0;r<4;r++) zw[r+4*rv]=v[r];
        __syncwarp();
        for(int j=lane;j<128;j+=32) dp[wf*128+j]=zw[j];
        __syncwarp();
    }
}

// ---------------- fused attention, 512 threads / 16 warps, 2 CTAs/SM ----------------
__global__ __launch_bounds__(512,2) void fused_attn_kernel(const float2* __restrict__ qkvb,
        const float* __restrict__ tmul, float* __restrict__ out){
    extern __shared__ float sm[];
    float* FBr=sm; float* FBi=FBr+8320;
    float2* Zt=(float2*)(FBi+8320); float2* Tw=Zt+16*128;
    __shared__ float red[32];
    const int p=blockIdx.x, b=p>>7, d=p&127;
    const int tid=threadIdx.x, lane=tid&31, wid=tid>>5;
    fill_tw(Tw,tid); __syncthreads();
    const float2* Qp=qkvb+(size_t)(b*384      +d)*NF;
    const float2* Kp=qkvb+(size_t)(b*384+128  +d)*NF;
    const float2* Vp=qkvb+(size_t)(b*384+256  +d)*NF;
    float2* zw=Zt+wid*128;
    const int rv=__brev(lane)>>27;
    for(int wf=wid;wf<WF;wf+=16){
        float2 v[4];
#pragma unroll
        for(int r=0;r<4;r++){
            int fi=wf*128+lane+32*r;
            float2 a=Qp[fi], bb=Kp[fi];
            v[r]=make_float2(a.x*bb.x+a.y*bb.y, a.y*bb.x-a.x*bb.y);
        }
        warp_fft128(v,Tw,lane);
#pragma unroll
        for(int r=0;r<4;r++){ int hh=r+4*rv; FBr[hh*WF+wf]=v[r].x; FBi[hh*WF+wf]=-v[r].y; }
    }
    __syncthreads();
    const float s1=1.0f/2097152.0f;
    for(int rp=wid;rp<64;rp+=16){
        int h0=2*rp, h1=h0+1;
        float2 v[4];
#pragma unroll
        for(int r=0;r<4;r++){
            int f=lane+32*r;
            if(f<WF){
                float g0x=FBr[h0*WF+f],g0y=FBi[h0*WF+f],g1x=FBr[h1*WF+f],g1y=FBi[h1*WF+f];
                v[r]=make_float2(g0x-g1y, -g0y-g1x);
            }else{
                int m=128-f;
                float g0x=FBr[h0*WF+m],g0y=FBi[h0*WF+m],g1x=FBr[h1*WF+m],g1y=FBi[h1*WF+m];
                v[r]=make_float2(g0x+g1y, g0y-g1x);
            }
        }
        warp_fft128(v,Tw,lane);
#pragma unroll
        for(int r=0;r<4;r++) zw[r+4*rv]=v[r];
        __syncwarp();
        for(int w=lane;w<128;w+=32){
            float2 z=zw[w];
            float v0=z.x*s1, v1=-z.y*s1;
            if(w<WF){ FBr[h0*WF+w]=v0; FBr[h1*WF+w]=v1; }
            else    { FBi[h0*WF+w-WF]=v0; FBi[h1*WF+w-WF]=v1; }
        }
        __syncwarp();
    }
    __syncthreads();
    float mx=-1e30f;
    for(int i=tid;i<NPIX;i+=512){
        int h=i>>7,w=i&127;
        float val=(w<WF)?FBr[h*WF+w]:FBi[h*WF+w-WF];
        mx=fmaxf(mx,val);
    }
    for(int o=16;o;o>>=1) mx=fmaxf(mx,__shfl_xor_sync(0xffffffffu,mx,o));
    if(lane==0) red[wid]=mx;
    __syncthreads();
    mx=red[0];
#pragma unroll
    for(int i=1;i<16;i++) mx=fmaxf(mx,red[i]);
    float s=0.f;
    for(int i=tid;i<NPIX;i+=512){
        int h=i>>7,w=i&127;
        float* a=(w<WF)?&FBr[h*WF+w]:&FBi[h*WF+w-WF];
        float e=expf(*a-mx); *a=e; s+=e;
    }
    for(int o=16;o;o>>=1) s+=__shfl_xor_sync(0xffffffffu,s,o);
    if(lane==0) red[16+wid]=s;
    __syncthreads();
    s=0.f;
#pragma unroll
    for(int i=0;i<16;i++) s+=red[16+i];
    float inv=1.0f/s;
    for(int i=tid;i<NPIX;i+=512){
        int h=i>>7,w=i&127;
        float* a=(w<WF)?&FBr[h*WF+w]:&FBi[h*WF+w-WF];
        *a*=inv;
    }
    __syncthreads();
    for(int rp=wid;rp<64;rp+=16){
        int r0=2*rp, r1=r0+1;
        float2 v[4];
#pragma unroll
        for(int r=0;r<4;r++){
            int j=lane+32*r;
            float a0=(j<WF)?FBr[r0*WF+j]:FBi[r0*WF+j-WF];
            float a1=(j<WF)?FBr[r1*WF+j]:FBi[r1*WF+j-WF];
            v[r]=make_float2(a0,a1);
        }
        warp_fft128(v,Tw,lane);
#pragma unroll
        for(int r=0;r<4;r++) zw[r+4*rv]=v[r];
        __syncwarp();
        for(int f=lane;f<WF;f+=32){
            float2 Zf=zw[f], Zm=zw[(128-f)&127];
            FBr[r0*WF+f]=0.5f*(Zf.x+Zm.x); FBi[r0*WF+f]=0.5f*(Zf.y-Zm.y);
            FBr[r1*WF+f]=0.5f*(Zf.y+Zm.y); FBi[r1*WF+f]=0.5f*(Zm.x-Zf.x);
        }
        __syncwarp();
    }
    __syncthreads();
    for(int wf=wid;wf<WF;wf+=16){
        float2 v[4];
#pragma unroll
        for(int r=0;r<4;r++){ int hh=lane+32*r; v[r]=make_float2(FBr[hh*WF+wf],FBi[hh*WF+wf]); }
        warp_fft128(v,Tw,lane);
#pragma unroll
        for(int r=0;r<4;r++) zw[r+4*rv]=v[r];
        __syncwarp();
#pragma unroll
        for(int r=0;r<4;r++){
            int k=lane+32*r;
            float2 A=zw[k], Vh=Vp[wf*128+k];
            v[r]=make_float2(A.x*Vh.x+A.y*Vh.y, A.y*Vh.x-A.x*Vh.y);
        }
        warp_fft128(v,Tw,lane);
#pragma unroll
        for(int r=0;r<4;r++){ int hh=r+4*rv; FBr[hh*WF+wf]=v[r].x; FBi[hh*WF+wf]=-v[r].y; }
        __syncwarp();
    }
    __syncthreads();
    const float s2=1.0f/16384.0f;
    float* op=out+(size_t)p*NPIX;
    const float* tp=tmul+(size_t)p*NPIX;
    for(int rp=wid;rp<64;rp+=16){
        int h0=2*rp, h1=h0+1;
        float2 v[4];
#pragma unroll
        for(int r=0;r<4;r++){
            int f=lane+32*r;
            if(f<WF){
                float g0x=FBr[h0*WF+f],g0y=FBi[h0*WF+f],g1x=FBr[h1*WF+f],g1y=FBi[h1*WF+f];
                v[r]=make_float2(g0x-g1y, -g0y-g1x);
            }else{
                int m=128-f;
                float g0x=FBr[h0*WF+m],g0y=FBi[h0*WF+m],g1x=FBr[h1*WF+m],g1y=FBi[h1*WF+m];
                v[r]=make_float2(g0x+g1y, g0y-g1x);
            }
        }
        warp_fft128(v,Tw,lane);
#pragma unroll
        for(int r=0;r<4;r++) zw[r+4*rv]=v[r];
        __syncwarp();
        for(int w=lane;w<128;w+=32){
            float2 z=zw[w];
            int i0=h0*128+w, i1=h1*128+w;
            op[i0]=z.x*s2*tp[i0];
            op[i1]=-z.y*s2*tp[i1];
        }
        __syncwarp();
    }
}

// ---------------- bf16 split ----------------
__device__ __forceinline__ uint32_t packsplit(float v){
    __nv_bfloat16 h=__float2bfloat16(v);
    float hf=__bfloat162float(h);
    __nv_bfloat16 l=__float2bfloat16(v-hf);
    return ((uint32_t)__bfloat16_as_ushort(h)<<16)|(uint32_t)__bfloat16_as_ushort(l);
}
__global__ void wpack(const float* __restrict__ src, uint32_t* __restrict__ dst, int n){
    int i=blockIdx.x*256+threadIdx.x;
    if(i<n) dst[i]=packsplit(src[i]);
}

// ---------------- hgemm: cp.async prefetch + multi-tile loop ----------------
#define KW 67
#define HS_WH 0
#define HS_WL (128*KW)
#define HS_XH (2*128*KW)
#define HS_XL (3*128*KW)
#define HS_STG (4*128*KW)
#define HSM_TOT ((4*128*KW + 128*132)*4)

__device__ __forceinline__ uint32_t smem_u32(const void* p){
    uint32_t a; asm("{ .reg .u64 t; cvta.to.shared.u64 t, %1; cvt.u32.u64 %0, t; }":"=r"(a):"l"(p));
    return a;
}
__device__ __forceinline__ void mma_bf16(float c[4], const uint32_t a[4], const uint32_t b[2]){
    asm volatile("mma.sync.aligned.m16n8k16.row.col.f32.bf16.bf16.f32 "
        "{%0,%1,%2,%3}, {%4,%5,%6,%7}, {%8,%9}, {%0,%1,%2,%3};"
        : "+f"(c[0]),"+f"(c[1]),"+f"(c[2]),"+f"(c[3])
        : "r"(a[0]),"r"(a[1]),"r"(a[2]),"r"(a[3]),"r"(b[0]),"r"(b[1]));
}
__device__ __forceinline__ void cp16(uint32_t saddr, const void* g){
    asm volatile("cp.async.cg.shared.global [%0], [%1], 16;"::"r"(saddr),"l"(g):"memory");
}

__global__ __launch_bounds__(512,1) void hgemm(const uint32_t* __restrict__ Wq,
        const float* __restrict__ Xf, size_t xs, float* __restrict__ Cb, size_t cs,
        int ld, const float* __restrict__ bias, int act, int nbat){
    extern __shared__ uint32_t hsm[];
    uint32_t* WH=hsm+HS_WH; uint32_t* WL=hsm+HS_WL;
    uint32_t* XH=hsm+HS_XH; uint32_t* XL=hsm+HS_XL;
    float* STG=(float*)(hsm+HS_STG);
    const uint32_t stg_b=smem_u32(STG);
    const int mt=blockIdx.y, nt=blockIdx.x, bz=blockIdx.z;
    const int tid=threadIdx.x, wid=tid>>5, lane=tid&31;
    const float* Xt0=Xf+(size_t)nt*128;

    {
        const float* Xp=Xt0+(size_t)(bz*nbat)*xs;
        for(int c=tid;c<4096;c+=512){
            int row=c>>5, col=(c&31)*4;
            cp16(stg_b+(uint32_t)(row*132+col)*4u, Xp+(size_t)row*ld+col);
        }
        asm volatile("cp.async.commit_group;":::"memory");
    }
    {
        const uint32_t* Wp=Wq+(size_t)mt*128*128;
        for(int idx=tid;idx<128*32;idx+=512){
            int row=idx>>5, c4=(idx&31)*4;
            uint4 w=*(const uint4*)&Wp[row*128+c4];
            uint32_t h0,l0,h1,l1;
            asm("prmt.b32 %0,%1,%2,0x7632;":"=r"(h0):"r"(w.x),"r"(w.y));
            asm("prmt.b32 %0,%1,%2,0x5410;":"=r"(l0):"r"(w.x),"r"(w.y));
            asm("prmt.b32 %0,%1,%2,0x7632;":"=r"(h1):"r"(w.z),"r"(w.w));
            asm("prmt.b32 %0,%1,%2,0x5410;":"=r"(l1):"r"(w.z),"r"(w.w));
            int wc=c4>>1;
            WH[row*KW+wc]=h0; WH[row*KW+wc+1]=h1;
            WL[row*KW+wc]=l0; WL[row*KW+wc+1]=l1;
        }
    }

    const int g=lane>>2, t=lane&3;
    const int warp_m=(wid>>2)*32, warp_n=(wid&3)*32;

    for(int nb=0;nb<nbat;nb++){
        const int b=bz*nbat+nb;
        asm volatile("cp.async.wait_group 0;":::"memory");
        __syncthreads();
        for(int idx=tid;idx<8192;idx+=512){
            int n=idx&127, wc=idx>>7;
            float f0=STG[(2*wc)*132+n], f1=STG[(2*wc+1)*132+n];
            uint32_t p0=packsplit(f0), p1=packsplit(f1);
            uint32_t hi,lo;
            asm("prmt.b32 %0,%1,%2,0x7632;":"=r"(hi):"r"(p0),"r"(p1));
            asm("prmt.b32 %0,%1,%2,0x5410;":"=r"(lo):"r"(p0),"r"(p1));
            XH[n*KW+wc]=hi; XL[n*KW+wc]=lo;
        }
        __syncthreads();
        if(nb+1<nbat){
            const float* Xp=Xt0+(size_t)(b+1)*xs;
            for(int c=tid;c<4096;c+=512){
                int row=c>>5, col=(c&31)*4;
                cp16(stg_b+(uint32_t)(row*132+col)*4u, Xp+(size_t)row*ld+col);
            }
            asm volatile("cp.async.commit_group;":::"memory");
        }

        float acc[2][4][4];
#pragma unroll
        for(int mi=0;mi<2;mi++)
#pragma unroll
            for(int ni=0;ni<4;ni++)
#pragma unroll
                for(int q=0;q<4;q++) acc[mi][ni][q]=0.f;

#pragma unroll
        for(int kk=0;kk<8;kk++){
            const int wt=kk*8+t;
            uint32_t bh[4][2], bl[4][2];
#pragma unroll
            for(int ni=0;ni<4;ni++){
                int n=warp_n+ni*8+g;
                bh[ni][0]=XH[n*KW+wt]; bh[ni][1]=XH[n*KW+wt+4];
                bl[ni][0]=XL[n*KW+wt]; bl[ni][1]=XL[n*KW+wt+4];
            }
#pragma unroll
            for(int mi=0;mi<2;mi++){
                int r0=warp_m+mi*16+g, r1=r0+8;
                uint32_t ah[4], al[4];
                ah[0]=WH[r0*KW+wt];   ah[1]=WH[r1*KW+wt];
                ah[2]=WH[r0*KW+wt+4]; ah[3]=WH[r1*KW+wt+4];
                al[0]=WL[r0*KW+wt];   al[1]=WL[r1*KW+wt];
                al[2]=WL[r0*KW+wt+4]; al[3]=WL[r1*KW+wt+4];
#pragma unroll
                for(int ni=0;ni<4;ni++){
                    mma_bf16(acc[mi][ni], ah, bh[ni]);
                    mma_bf16(acc[mi][ni], ah, bl[ni]);
                    mma_bf16(acc[mi][ni], al, bh[ni]);
                }
            }
        }

        float* C=Cb+(size_t)b*cs+(size_t)(mt*128)*ld+(size_t)nt*128;
#pragma unroll
        for(int mi=0;mi<2;mi++){
            int m0=warp_m+mi*16+g, m1=m0+8;
            float bv0=bias?bias[mt*128+m0]:0.f;
            float bv1=bias?bias[mt*128+m1]:0.f;
#pragma unroll
            for(int ni=0;ni<4;ni++){
                int cn=warp_n+ni*8+2*t;
                float v0=acc[mi][ni][0]+bv0, v1=acc[mi][ni][1]+bv0;
                float v2=acc[mi][ni][2]+bv1, v3=acc[mi][ni][3]+bv1;
                if(act){
                    v0=v0/(1.0f+expf(-v0)); v1=v1/(1.0f+expf(-v1));
                    v2=v2/(1.0f+expf(-v2)); v3=v3/(1.0f+expf(-v3));
                }
                *(float2*)&C[(size_t)m0*ld+cn]=make_float2(v0,v1);
                *(float2*)&C[(size_t)m1*ld+cn]=make_float2(v2,v3);
            }
        }
    }
}

extern "C" void kernel_launch(void* const* d_in, const int* in_sizes, int n_in, void* d_out, int out_size){
    const float* x     =(const float*)d_in[0];
    const float* w_qkv =(const float*)d_in[1];
    const float* w_gate=(const float*)d_in[2];
    const float* b_gate=(const float*)d_in[3];
    const float* w_proj=(const float*)d_in[4];
    const float* b_proj=(const float*)d_in[5];
    float* out=(float*)d_out;

    cudaFuncSetAttribute(fwd_rfft2_kernel, cudaFuncAttributeMaxDynamicSharedMemorySize, SMEM_FFT2);
    cudaFuncSetAttribute(fused_attn_kernel, cudaFuncAttributeMaxDynamicSharedMemorySize, SMEM_FFT2);
    cudaFuncSetAttribute(hgemm, cudaFuncAttributeMaxDynamicSharedMemorySize, HSM_TOT);

    float2* xhat; cudaGetSymbolAddress((void**)&xhat, g_xhat);
    float2* qkv;  cudaGetSymbolAddress((void**)&qkv,  g_qkv);
    float*  tg;   cudaGetSymbolAddress((void**)&tg,   g_t);
    float*  attn; cudaGetSymbolAddress((void**)&attn, g_attn);
    uint32_t* wp; cudaGetSymbolAddress((void**)&wp,   g_wpk);

    uint32_t* wq=wp;
    uint32_t* wg=wp+384*128;
    uint32_t* wpj=wp+512*128;

    const size_t psN=(size_t)128*NPIX;
    const size_t fsX=(size_t)128*2*NF;
    const size_t fsQ=(size_t)384*2*NF;
    dim3 t512(512);

    wpack<<<192,256>>>(w_qkv, wq, 384*128);
    wpack<<<64,256>>>(w_gate, wg, 128*128);
    wpack<<<64,256>>>(w_proj, wpj, 128*128);

    hgemm<<<dim3(128,1,1),t512,HSM_TOT>>>(wg, x, psN, tg, psN, NPIX, b_gate, 1, 8);
    fwd_rfft2_kernel<<<1024,t512,SMEM_FFT2>>>(x, xhat);
    hgemm<<<dim3(130,3,1),t512,HSM_TOT>>>(wq, (const float*)xhat, fsX, (float*)qkv, fsQ, 16640, 0, 0, 8);
    fused_attn_kernel<<<1024,t512,SMEM_FFT2>>>(qkv, tg, attn);
    hgemm<<<dim3(128,1,1),t512,HSM_TOT>>>(wpj, attn, psN, out, psN, NPIX, b_proj, 0, 8);
}